// round 3
// baseline (speedup 1.0000x reference)
#include <cuda_runtime.h>
#include <math.h>

// Problem constants
#define B_ 128
#define T_ 512
#define C_ 512
#define TC_ (T_ * C_)          // 262144
#define M_ (B_ * T_)           // 65536
#define H_ (2 * C_)            // 1024
#define EPS_ 1e-5f

// ---------------- scratch (static device arrays; no allocation) ----------------
__device__ float g_x [(size_t)B_ * TC_];   // ln1 output
__device__ float g_z [(size_t)B_ * TC_];   // triu-mix + inputs (ln2 input)
__device__ float g_x2[(size_t)B_ * TC_];   // ln2 output
__device__ float g_h [(size_t)M_ * H_];    // gelu(fc1) activations
__device__ float g_mu  [2 * B_];
__device__ float g_rstd[2 * B_];

// ---------------- per-batch joint (T,C) layernorm stats ----------------
// which==0: read from src (the harness input). which==1: read from g_z.
__global__ void stats_kernel(const float* __restrict__ src, int which) {
    int b   = blockIdx.x;
    int tid = threadIdx.x;
    const float* base = (which == 0) ? src : g_z;
    const float4* p = reinterpret_cast<const float4*>(base + (size_t)b * TC_);
    float sx = 0.f, sy = 0.f, sz = 0.f, sw = 0.f;
    float qx = 0.f, qy = 0.f, qz = 0.f, qw = 0.f;
    for (int i = tid; i < TC_ / 4; i += 256) {
        float4 v = p[i];
        sx += v.x; sy += v.y; sz += v.z; sw += v.w;
        qx = fmaf(v.x, v.x, qx);
        qy = fmaf(v.y, v.y, qy);
        qz = fmaf(v.z, v.z, qz);
        qw = fmaf(v.w, v.w, qw);
    }
    __shared__ double sh [256];
    __shared__ double sh2[256];
    sh [tid] = (double)sx + (double)sy + (double)sz + (double)sw;
    sh2[tid] = (double)qx + (double)qy + (double)qz + (double)qw;
    __syncthreads();
    for (int off = 128; off > 0; off >>= 1) {
        if (tid < off) { sh[tid] += sh[tid + off]; sh2[tid] += sh2[tid + off]; }
        __syncthreads();
    }
    if (tid == 0) {
        double m   = sh[0]  / (double)TC_;
        double var = sh2[0] / (double)TC_ - m * m;
        g_mu  [which * B_ + b] = (float)m;
        g_rstd[which * B_ + b] = (float)(1.0 / sqrt(var + (double)EPS_));
    }
}

// ---------------- ln1 apply: g_x = (inp - mu0) * rstd0 * w + b ----------------
__global__ void apply_ln1(const float* __restrict__ src,
                          const float* __restrict__ w,
                          const float* __restrict__ bias) {
    int i = blockIdx.x * blockDim.x + threadIdx.x;   // float4 index
    int total = B_ * TC_ / 4;
    if (i >= total) return;
    int b = i / (TC_ / 4);
    int r = i % (TC_ / 4);
    float mu = g_mu[b];
    float rs = g_rstd[b];
    float4 v  = reinterpret_cast<const float4*>(src)[i];
    float4 wv = reinterpret_cast<const float4*>(w)[r];
    float4 bv = reinterpret_cast<const float4*>(bias)[r];
    v.x = fmaf((v.x - mu) * rs, wv.x, bv.x);
    v.y = fmaf((v.y - mu) * rs, wv.y, bv.y);
    v.z = fmaf((v.z - mu) * rs, wv.z, bv.z);
    v.w = fmaf((v.w - mu) * rs, wv.w, bv.w);
    reinterpret_cast<float4*>(g_x)[i] = v;
}

// ---------------- ln2 apply: g_x2 = (g_z - mu1) * rstd1 * w + b ----------------
__global__ void apply_ln2(const float* __restrict__ w,
                          const float* __restrict__ bias) {
    int i = blockIdx.x * blockDim.x + threadIdx.x;
    int total = B_ * TC_ / 4;
    if (i >= total) return;
    int b = i / (TC_ / 4);
    int r = i % (TC_ / 4);
    float mu = g_mu[B_ + b];
    float rs = g_rstd[B_ + b];
    float4 v  = reinterpret_cast<const float4*>(g_z)[i];
    float4 wv = reinterpret_cast<const float4*>(w)[r];
    float4 bv = reinterpret_cast<const float4*>(bias)[r];
    v.x = fmaf((v.x - mu) * rs, wv.x, bv.x);
    v.y = fmaf((v.y - mu) * rs, wv.y, bv.y);
    v.z = fmaf((v.z - mu) * rs, wv.z, bv.z);
    v.w = fmaf((v.w - mu) * rs, wv.w, bv.w);
    reinterpret_cast<float4*>(g_x2)[i] = v;
}

// ---------------- batched causal TriU mix:
// g_z[b,s,c] = sum_{t<=s} W[s,t] * g_x[b,t,c] + triu_b[s] + inputs[b,s,c]
// A = W [T,T] row-major (k-contig, NN), B = g_x[b] [T,C] (n-contig, NN)
__global__ void __launch_bounds__(256, 2)
gemm_triu(const float* __restrict__ W, const float* __restrict__ tb,
          const float* __restrict__ inp) {
    int bx = blockIdx.x, by = blockIdx.y, bz = blockIdx.z;
    const float* X = g_x + (size_t)bz * TC_;
    const float* I = inp + (size_t)bz * TC_;
    float*       Z = g_z + (size_t)bz * TC_;

    __shared__ float As[8][128];
    __shared__ float Bs[8][128];

    int tid = threadIdx.x;
    int tm = tid >> 4, tn = tid & 15;

    float acc[8][8];
#pragma unroll
    for (int i = 0; i < 8; ++i)
#pragma unroll
        for (int j = 0; j < 8; ++j) acc[i][j] = 0.f;

    int arow_l = tid >> 1;                 // 0..127
    int arow   = by * 128 + arow_l;        // global s
    int acol4  = (tid & 1) * 4;            // 0 or 4
    int bk_l   = tid >> 5;                 // 0..7
    int bcol_l = (tid & 31) * 4;           // 0..124
    int bcol   = bx * 128 + bcol_l;

    int ktiles = (by + 1) * 16;            // triangular early-exit

    for (int kt = 0; kt < ktiles; ++kt) {
        int k0 = kt * 8;
        // A tile (masked tril)
        float4 a = *reinterpret_cast<const float4*>(W + (size_t)arow * T_ + k0 + acol4);
        int kb = k0 + acol4;
        if (kb + 0 > arow) a.x = 0.f;
        if (kb + 1 > arow) a.y = 0.f;
        if (kb + 2 > arow) a.z = 0.f;
        if (kb + 3 > arow) a.w = 0.f;
        As[acol4 + 0][arow_l] = a.x;
        As[acol4 + 1][arow_l] = a.y;
        As[acol4 + 2][arow_l] = a.z;
        As[acol4 + 3][arow_l] = a.w;
        // B tile (n-contiguous)
        float4 bvec = *reinterpret_cast<const float4*>(X + (size_t)(k0 + bk_l) * C_ + bcol);
        *reinterpret_cast<float4*>(&Bs[bk_l][bcol_l]) = bvec;
        __syncthreads();
#pragma unroll
        for (int kk = 0; kk < 8; ++kk) {
            float af[8], bf[8];
            *reinterpret_cast<float4*>(&af[0]) = *reinterpret_cast<const float4*>(&As[kk][tm * 8]);
            *reinterpret_cast<float4*>(&af[4]) = *reinterpret_cast<const float4*>(&As[kk][tm * 8 + 4]);
            *reinterpret_cast<float4*>(&bf[0]) = *reinterpret_cast<const float4*>(&Bs[kk][tn * 8]);
            *reinterpret_cast<float4*>(&bf[4]) = *reinterpret_cast<const float4*>(&Bs[kk][tn * 8 + 4]);
#pragma unroll
            for (int i = 0; i < 8; ++i)
#pragma unroll
                for (int j = 0; j < 8; ++j)
                    acc[i][j] = fmaf(af[i], bf[j], acc[i][j]);
        }
        __syncthreads();
    }

#pragma unroll
    for (int i = 0; i < 8; ++i) {
        int m = by * 128 + tm * 8 + i;
        float add = tb[m];
#pragma unroll
        for (int j = 0; j < 8; ++j) {
            int n = bx * 128 + tn * 8 + j;
            size_t idx = (size_t)m * C_ + n;
            Z[idx] = acc[i][j] + add + I[idx];
        }
    }
}

// ---------------- fc1: g_h = gelu(g_x2 @ fc1_W^T + fc1_b)  (NT gemm)
// A = g_x2 [M_, C_] (k-contig), B = fc1_W [H_, C_] (k-contig)
__global__ void __launch_bounds__(256, 2)
gemm_fc1(const float* __restrict__ Wt, const float* __restrict__ b1) {
    int bx = blockIdx.x, by = blockIdx.y;
    __shared__ float As[8][128];
    __shared__ float Bs[8][128];
    int tid = threadIdx.x;
    int tm = tid >> 4, tn = tid & 15;

    float acc[8][8];
#pragma unroll
    for (int i = 0; i < 8; ++i)
#pragma unroll
        for (int j = 0; j < 8; ++j) acc[i][j] = 0.f;

    int row_l = tid >> 1;
    int col4  = (tid & 1) * 4;
    int arow  = by * 128 + row_l;          // global m
    int brow  = bx * 128 + row_l;          // global n

    for (int kt = 0; kt < C_ / 8; ++kt) {
        int k0 = kt * 8;
        float4 a = *reinterpret_cast<const float4*>(g_x2 + (size_t)arow * C_ + k0 + col4);
        As[col4 + 0][row_l] = a.x;
        As[col4 + 1][row_l] = a.y;
        As[col4 + 2][row_l] = a.z;
        As[col4 + 3][row_l] = a.w;
        float4 b = *reinterpret_cast<const float4*>(Wt + (size_t)brow * C_ + k0 + col4);
        Bs[col4 + 0][row_l] = b.x;
        Bs[col4 + 1][row_l] = b.y;
        Bs[col4 + 2][row_l] = b.z;
        Bs[col4 + 3][row_l] = b.w;
        __syncthreads();
#pragma unroll
        for (int kk = 0; kk < 8; ++kk) {
            float af[8], bf[8];
            *reinterpret_cast<float4*>(&af[0]) = *reinterpret_cast<const float4*>(&As[kk][tm * 8]);
            *reinterpret_cast<float4*>(&af[4]) = *reinterpret_cast<const float4*>(&As[kk][tm * 8 + 4]);
            *reinterpret_cast<float4*>(&bf[0]) = *reinterpret_cast<const float4*>(&Bs[kk][tn * 8]);
            *reinterpret_cast<float4*>(&bf[4]) = *reinterpret_cast<const float4*>(&Bs[kk][tn * 8 + 4]);
#pragma unroll
            for (int i = 0; i < 8; ++i)
#pragma unroll
                for (int j = 0; j < 8; ++j)
                    acc[i][j] = fmaf(af[i], bf[j], acc[i][j]);
        }
        __syncthreads();
    }

#pragma unroll
    for (int i = 0; i < 8; ++i) {
        int m = by * 128 + tm * 8 + i;
#pragma unroll
        for (int j = 0; j < 8; ++j) {
            int n = bx * 128 + tn * 8 + j;
            float v = acc[i][j] + b1[n];
            // exact GELU
            v = 0.5f * v * (1.0f + erff(v * 0.70710678118654752f));
            g_h[(size_t)m * H_ + n] = v;
        }
    }
}

// ---------------- fc2: out = g_h @ fc2_W^T + fc2_b + g_x2  (NT gemm)
// A = g_h [M_, H_] (k-contig), B = fc2_W [C_, H_] (k-contig)
__global__ void __launch_bounds__(256, 2)
gemm_fc2(const float* __restrict__ Wt, const float* __restrict__ b2,
         float* __restrict__ out) {
    int bx = blockIdx.x, by = blockIdx.y;
    __shared__ float As[8][128];
    __shared__ float Bs[8][128];
    int tid = threadIdx.x;
    int tm = tid >> 4, tn = tid & 15;

    float acc[8][8];
#pragma unroll
    for (int i = 0; i < 8; ++i)
#pragma unroll
        for (int j = 0; j < 8; ++j) acc[i][j] = 0.f;

    int row_l = tid >> 1;
    int col4  = (tid & 1) * 4;
    int arow  = by * 128 + row_l;
    int brow  = bx * 128 + row_l;

    for (int kt = 0; kt < H_ / 8; ++kt) {
        int k0 = kt * 8;
        float4 a = *reinterpret_cast<const float4*>(g_h + (size_t)arow * H_ + k0 + col4);
        As[col4 + 0][row_l] = a.x;
        As[col4 + 1][row_l] = a.y;
        As[col4 + 2][row_l] = a.z;
        As[col4 + 3][row_l] = a.w;
        float4 b = *reinterpret_cast<const float4*>(Wt + (size_t)brow * H_ + k0 + col4);
        Bs[col4 + 0][row_l] = b.x;
        Bs[col4 + 1][row_l] = b.y;
        Bs[col4 + 2][row_l] = b.z;
        Bs[col4 + 3][row_l] = b.w;
        __syncthreads();
#pragma unroll
        for (int kk = 0; kk < 8; ++kk) {
            float af[8], bf[8];
            *reinterpret_cast<float4*>(&af[0]) = *reinterpret_cast<const float4*>(&As[kk][tm * 8]);
            *reinterpret_cast<float4*>(&af[4]) = *reinterpret_cast<const float4*>(&As[kk][tm * 8 + 4]);
            *reinterpret_cast<float4*>(&bf[0]) = *reinterpret_cast<const float4*>(&Bs[kk][tn * 8]);
            *reinterpret_cast<float4*>(&bf[4]) = *reinterpret_cast<const float4*>(&Bs[kk][tn * 8 + 4]);
#pragma unroll
            for (int i = 0; i < 8; ++i)
#pragma unroll
                for (int j = 0; j < 8; ++j)
                    acc[i][j] = fmaf(af[i], bf[j], acc[i][j]);
        }
        __syncthreads();
    }

#pragma unroll
    for (int i = 0; i < 8; ++i) {
        int m = by * 128 + tm * 8 + i;
#pragma unroll
        for (int j = 0; j < 8; ++j) {
            int n = bx * 128 + tn * 8 + j;
            size_t idx = (size_t)m * C_ + n;
            out[idx] = acc[i][j] + b2[n] + g_x2[idx];
        }
    }
}

// ---------------- launch ----------------
extern "C" void kernel_launch(void* const* d_in, const int* in_sizes, int n_in,
                              void* d_out, int out_size) {
    (void)in_sizes; (void)n_in; (void)out_size;
    const float* inp    = (const float*)d_in[0];
    const float* ln1_w  = (const float*)d_in[1];
    const float* ln1_b  = (const float*)d_in[2];
    const float* ln2_w  = (const float*)d_in[3];
    const float* ln2_b  = (const float*)d_in[4];
    const float* triu_W = (const float*)d_in[5];
    const float* triu_b = (const float*)d_in[6];
    const float* fc1_W  = (const float*)d_in[7];
    const float* fc1_b  = (const float*)d_in[8];
    const float* fc2_W  = (const float*)d_in[9];
    const float* fc2_b  = (const float*)d_in[10];
    float* out = (float*)d_out;

    int ew_blocks = (B_ * TC_ / 4 + 255) / 256;

    // 1. ln1: stats over inputs, apply -> g_x
    stats_kernel<<<B_, 256>>>(inp, 0);
    apply_ln1<<<ew_blocks, 256>>>(inp, ln1_w, ln1_b);

    // 2. TriU causal mix (+bias +residual inputs) -> g_z
    gemm_triu<<<dim3(C_ / 128, T_ / 128, B_), 256>>>(triu_W, triu_b, inp);

    // 3. ln2: stats over g_z, apply -> g_x2
    stats_kernel<<<B_, 256>>>(inp /*unused for which=1*/, 1);
    apply_ln2<<<ew_blocks, 256>>>(ln2_w, ln2_b);

    // 4. fc1 + exact GELU -> g_h
    gemm_fc1<<<dim3(H_ / 128, M_ / 128), 256>>>(fc1_W, fc1_b);

    // 5. fc2 + bias + residual(g_x2) -> out
    gemm_fc2<<<dim3(C_ / 128, M_ / 128), 256>>>(fc2_W, fc2_b, out);
}

// round 8
// speedup vs baseline: 2.2101x; 2.2101x over previous
#include <cuda_runtime.h>
#include <cuda_bf16.h>
#include <math.h>
#include <stdint.h>

// ---------------- problem constants ----------------
#define B_ 128
#define T_ 512
#define C_ 512
#define TC_ (T_ * C_)          // 262144
#define M_ (B_ * T_)           // 65536
#define H_ (2 * C_)            // 1024
#define EPS_ 1e-5f

#define KCE 64                  // k elements per chunk (64 bf16 = 128B row)
#define STG_B 32768             // stage bytes: A tile 16KB + B tile 16KB
#define DYN_SMEM (2 * STG_B)    // 64KB double buffered
#define NTHR 512                // 16 warps

// ---------------- scratch (static device arrays; no allocation) ----------------
__device__ float g_z [(size_t)B_ * TC_];           // triu out + residual (ln2 input)
__device__ __nv_bfloat16 g_x2h[(size_t)B_ * TC_];  // ln2 output hi
__device__ __nv_bfloat16 g_x2l[(size_t)B_ * TC_];  // ln2 output lo
__device__ __nv_bfloat16 g_xTh[(size_t)B_ * TC_];  // ln1 out transposed [b][c][t] hi
__device__ __nv_bfloat16 g_xTl[(size_t)B_ * TC_];  // lo
__device__ __nv_bfloat16 g_hh[(size_t)M_ * H_];    // gelu(fc1) hi
__device__ __nv_bfloat16 g_hl[(size_t)M_ * H_];    // lo
__device__ __nv_bfloat16 g_wh[(size_t)T_ * T_];    // tril(triu_W) hi
__device__ __nv_bfloat16 g_wl[(size_t)T_ * T_];    // lo
__device__ __nv_bfloat16 g_f1h[(size_t)H_ * C_];   // fc1_W hi
__device__ __nv_bfloat16 g_f1l[(size_t)H_ * C_];
__device__ __nv_bfloat16 g_f2h[(size_t)C_ * H_];   // fc2_W hi
__device__ __nv_bfloat16 g_f2l[(size_t)C_ * H_];
__device__ float g_mu  [2 * B_];
__device__ float g_rstd[2 * B_];

// ---------------- small helpers ----------------
__device__ __forceinline__ uint32_t su32(const void* p) {
    uint32_t a;
    asm("{ .reg .u64 t; cvta.to.shared.u64 t, %1; cvt.u32.u64 %0, t; }" : "=r"(a) : "l"(p));
    return a;
}
__device__ __forceinline__ void cp16(uint32_t saddr, const void* g) {
    asm volatile("cp.async.cg.shared.global [%0], [%1], 16;" :: "r"(saddr), "l"(g));
}
__device__ __forceinline__ void cp_commit() {
    asm volatile("cp.async.commit_group;" ::: "memory");
}
__device__ __forceinline__ void cp_wait1() {
    asm volatile("cp.async.wait_group 1;" ::: "memory");
}
__device__ __forceinline__ void cp_wait0() {
    asm volatile("cp.async.wait_group 0;" ::: "memory");
}
__device__ __forceinline__ void ldm_x4(uint32_t& r0, uint32_t& r1, uint32_t& r2, uint32_t& r3,
                                       uint32_t addr) {
    asm volatile("ldmatrix.sync.aligned.m8n8.x4.shared.b16 {%0,%1,%2,%3}, [%4];"
                 : "=r"(r0), "=r"(r1), "=r"(r2), "=r"(r3) : "r"(addr));
}
__device__ __forceinline__ void mma_bf16(float& d0, float& d1, float& d2, float& d3,
                                         uint32_t a0, uint32_t a1, uint32_t a2, uint32_t a3,
                                         uint32_t b0, uint32_t b1) {
    asm volatile(
        "mma.sync.aligned.m16n8k16.row.col.f32.bf16.bf16.f32 "
        "{%0,%1,%2,%3}, {%4,%5,%6,%7}, {%8,%9}, {%0,%1,%2,%3};"
        : "+f"(d0), "+f"(d1), "+f"(d2), "+f"(d3)
        : "r"(a0), "r"(a1), "r"(a2), "r"(a3), "r"(b0), "r"(b1));
}
__device__ __forceinline__ void split_bf16(float v, unsigned short& h, unsigned short& l) {
    __nv_bfloat16 bh = __float2bfloat16(v);
    float fh = __bfloat162float(bh);
    __nv_bfloat16 bl = __float2bfloat16(v - fh);
    h = __bfloat16_as_ushort(bh);
    l = __bfloat16_as_ushort(bl);
}
__device__ __forceinline__ float gelu_exact(float v) {
    return 0.5f * v * (1.0f + erff(v * 0.70710678118654752f));
}

// ---------------- GEMM mainloop pieces ----------------
// smem tile: 128 rows x 128 bytes, swizzled: sw = off ^ ((off>>3)&0x70)
__device__ __forceinline__ void load_chunk(uint32_t sA, uint32_t sB,
                                           const __nv_bfloat16* __restrict__ A, int am0, int lda,
                                           const __nv_bfloat16* __restrict__ Bsrc, int bn0, int ldb,
                                           int k0, int tid) {
#pragma unroll
    for (int it = 0; it < 2; ++it) {
        int idx = it * NTHR + tid;                 // 0..1023
        int r = idx >> 3, g = idx & 7;
        uint32_t off = (r << 7) + (g << 4);
        uint32_t sw = off ^ ((off >> 3) & 0x70);
        cp16(sA + sw, A + (size_t)(am0 + r) * lda + k0 + g * 8);
        cp16(sB + sw, Bsrc + (size_t)(bn0 + r) * ldb + k0 + g * 8);
    }
    cp_commit();
}

// compute one 128x128x64 stage; warp (wm 0..3, wn 0..3) owns 32x32
__device__ __forceinline__ void compute_stage(uint32_t sA, uint32_t sB, int wm, int wn, int lane,
                                              float acc[2][4][4]) {
#pragma unroll
    for (int ks = 0; ks < 4; ++ks) {
        uint32_t a[2][4];
#pragma unroll
        for (int mt = 0; mt < 2; ++mt) {
            int row = wm * 32 + mt * 16 + (lane & 15);
            int col = ks * 32 + ((lane >> 4) << 4);     // bytes
            uint32_t off = (row << 7) + col;
            off ^= (off >> 3) & 0x70;
            ldm_x4(a[mt][0], a[mt][1], a[mt][2], a[mt][3], sA + off);
        }
#pragma unroll
        for (int nt = 0; nt < 2; ++nt) {
            int row = wn * 32 + nt * 16 + ((lane >> 4) << 3) + (lane & 7);
            int col = ks * 32 + (((lane >> 3) & 1) << 4);  // bytes
            uint32_t off = (row << 7) + col;
            off ^= (off >> 3) & 0x70;
            uint32_t b0, b1, b2, b3;
            ldm_x4(b0, b1, b2, b3, sB + off);
#pragma unroll
            for (int mt = 0; mt < 2; ++mt) {
                mma_bf16(acc[mt][2 * nt + 0][0], acc[mt][2 * nt + 0][1],
                         acc[mt][2 * nt + 0][2], acc[mt][2 * nt + 0][3],
                         a[mt][0], a[mt][1], a[mt][2], a[mt][3], b0, b1);
                mma_bf16(acc[mt][2 * nt + 1][0], acc[mt][2 * nt + 1][1],
                         acc[mt][2 * nt + 1][2], acc[mt][2 * nt + 1][3],
                         a[mt][0], a[mt][1], a[mt][2], a[mt][3], b2, b3);
            }
        }
    }
}

// 3-pass hi/lo K-extended mainloop: p0=Ah*Bh, p1=Al*Bh, p2=Ah*Bl
#define GEMM_MAINLOOP(AH, AL, BH, BL, AM0, LDA, BN0, LDB, NK)                              \
    int nk = (NK);                                                                          \
    int ntot = 3 * nk;                                                                      \
    float acc[2][4][4];                                                                     \
    _Pragma("unroll") for (int i_ = 0; i_ < 2; ++i_)                                        \
    _Pragma("unroll") for (int j_ = 0; j_ < 4; ++j_)                                        \
    _Pragma("unroll") for (int e_ = 0; e_ < 4; ++e_) acc[i_][j_][e_] = 0.f;                 \
    load_chunk(sbase, sbase + 16384, (AH), (AM0), (LDA), (BH), (BN0), (LDB), 0, tid);       \
    for (int q = 0; q < ntot; ++q) {                                                        \
        if (q + 1 < ntot) {                                                                 \
            int qn = q + 1;                                                                 \
            int p_ = qn / nk;                                                               \
            int k0_ = (qn - p_ * nk) * KCE;                                                 \
            const __nv_bfloat16* As_ = (p_ == 1) ? (AL) : (AH);                             \
            const __nv_bfloat16* Bs_ = (p_ == 2) ? (BL) : (BH);                             \
            uint32_t sb = sbase + (qn & 1) * STG_B;                                         \
            load_chunk(sb, sb + 16384, As_, (AM0), (LDA), Bs_, (BN0), (LDB), k0_, tid);     \
            cp_wait1();                                                                     \
        } else {                                                                            \
            cp_wait0();                                                                     \
        }                                                                                   \
        __syncthreads();                                                                    \
        uint32_t sc = sbase + (q & 1) * STG_B;                                              \
        compute_stage(sc, sc + 16384, wm, wn, lane, acc);                                   \
        __syncthreads();                                                                    \
    }

// ---------------- TriU GEMM: g_z[b,s,c] = sum_{t<=s} W[s,t]*x[b,t,c] + tb[s] + inp[b,s,c]
__global__ void __launch_bounds__(NTHR, 1)
gemm_triu_mma(const float* __restrict__ tb, const float* __restrict__ inp) {
    extern __shared__ __align__(128) char dyn[];
    uint32_t sbase = su32(dyn);
    int tid = threadIdx.x, lane = tid & 31, w = tid >> 5, wm = w & 3, wn = w >> 2;
    int bx = blockIdx.x, by = blockIdx.y, bz = blockIdx.z;
    int m0 = by * 128, n0 = bx * 128;
    const __nv_bfloat16* Bh = g_xTh + (size_t)bz * TC_;
    const __nv_bfloat16* Bl = g_xTl + (size_t)bz * TC_;

    GEMM_MAINLOOP(g_wh, g_wl, Bh, Bl, m0, T_, n0, T_, 2 * (by + 1))

    float* Z = g_z + (size_t)bz * TC_;
    const float* I = inp + (size_t)bz * TC_;
#pragma unroll
    for (int mt = 0; mt < 2; ++mt) {
        int m = m0 + wm * 32 + mt * 16 + (lane >> 2);
        float tbm = tb[m], tbm8 = tb[m + 8];
#pragma unroll
        for (int nt = 0; nt < 4; ++nt) {
            int n = n0 + wn * 32 + nt * 8 + 2 * (lane & 3);
            size_t i0 = (size_t)m * C_ + n;
            size_t i8 = (size_t)(m + 8) * C_ + n;
            float2 r0 = *reinterpret_cast<const float2*>(I + i0);
            float2 r8 = *reinterpret_cast<const float2*>(I + i8);
            float2 o0, o8;
            o0.x = acc[mt][nt][0] + tbm + r0.x;
            o0.y = acc[mt][nt][1] + tbm + r0.y;
            o8.x = acc[mt][nt][2] + tbm8 + r8.x;
            o8.y = acc[mt][nt][3] + tbm8 + r8.y;
            *reinterpret_cast<float2*>(Z + i0) = o0;
            *reinterpret_cast<float2*>(Z + i8) = o8;
        }
    }
}

// ---------------- fc1 GEMM: h = gelu(x2 @ fc1_W^T + b1) -> hi/lo bf16
__global__ void __launch_bounds__(NTHR, 1)
gemm_fc1_mma(const float* __restrict__ b1) {
    extern __shared__ __align__(128) char dyn[];
    uint32_t sbase = su32(dyn);
    int tid = threadIdx.x, lane = tid & 31, w = tid >> 5, wm = w & 3, wn = w >> 2;
    int bx = blockIdx.x, by = blockIdx.y;
    int m0 = by * 128, n0 = bx * 128;

    GEMM_MAINLOOP(g_x2h, g_x2l, g_f1h, g_f1l, m0, C_, n0, C_, C_ / KCE)

#pragma unroll
    for (int mt = 0; mt < 2; ++mt) {
        int m = m0 + wm * 32 + mt * 16 + (lane >> 2);
#pragma unroll
        for (int nt = 0; nt < 4; ++nt) {
            int n = n0 + wn * 32 + nt * 8 + 2 * (lane & 3);
            float bn0v = b1[n], bn1v = b1[n + 1];
            float v0 = gelu_exact(acc[mt][nt][0] + bn0v);
            float v1 = gelu_exact(acc[mt][nt][1] + bn1v);
            float v2 = gelu_exact(acc[mt][nt][2] + bn0v);
            float v3 = gelu_exact(acc[mt][nt][3] + bn1v);
            unsigned short h0, l0, h1, l1, h2, l2, h3, l3;
            split_bf16(v0, h0, l0);
            split_bf16(v1, h1, l1);
            split_bf16(v2, h2, l2);
            split_bf16(v3, h3, l3);
            size_t i0 = (size_t)m * H_ + n;
            size_t i8 = (size_t)(m + 8) * H_ + n;
            *reinterpret_cast<uint32_t*>(g_hh + i0) = (uint32_t)h0 | ((uint32_t)h1 << 16);
            *reinterpret_cast<uint32_t*>(g_hl + i0) = (uint32_t)l0 | ((uint32_t)l1 << 16);
            *reinterpret_cast<uint32_t*>(g_hh + i8) = (uint32_t)h2 | ((uint32_t)h3 << 16);
            *reinterpret_cast<uint32_t*>(g_hl + i8) = (uint32_t)l2 | ((uint32_t)l3 << 16);
        }
    }
}

// ---------------- fc2 GEMM: out = h @ fc2_W^T + b2 + x2 (residual from hi+lo)
__global__ void __launch_bounds__(NTHR, 1)
gemm_fc2_mma(const float* __restrict__ b2, float* __restrict__ out) {
    extern __shared__ __align__(128) char dyn[];
    uint32_t sbase = su32(dyn);
    int tid = threadIdx.x, lane = tid & 31, w = tid >> 5, wm = w & 3, wn = w >> 2;
    int bx = blockIdx.x, by = blockIdx.y;
    int m0 = by * 128, n0 = bx * 128;

    GEMM_MAINLOOP(g_hh, g_hl, g_f2h, g_f2l, m0, H_, n0, H_, H_ / KCE)

#pragma unroll
    for (int mt = 0; mt < 2; ++mt) {
        int m = m0 + wm * 32 + mt * 16 + (lane >> 2);
#pragma unroll
        for (int nt = 0; nt < 4; ++nt) {
            int n = n0 + wn * 32 + nt * 8 + 2 * (lane & 3);
            float bn0v = b2[n], bn1v = b2[n + 1];
            size_t i0 = (size_t)m * C_ + n;
            size_t i8 = (size_t)(m + 8) * C_ + n;
            uint32_t xh0 = *reinterpret_cast<const uint32_t*>(g_x2h + i0);
            uint32_t xl0 = *reinterpret_cast<const uint32_t*>(g_x2l + i0);
            uint32_t xh8 = *reinterpret_cast<const uint32_t*>(g_x2h + i8);
            uint32_t xl8 = *reinterpret_cast<const uint32_t*>(g_x2l + i8);
            float x00 = __bfloat162float(__ushort_as_bfloat16((unsigned short)(xh0 & 0xFFFF)))
                      + __bfloat162float(__ushort_as_bfloat16((unsigned short)(xl0 & 0xFFFF)));
            float x01 = __bfloat162float(__ushort_as_bfloat16((unsigned short)(xh0 >> 16)))
                      + __bfloat162float(__ushort_as_bfloat16((unsigned short)(xl0 >> 16)));
            float x80 = __bfloat162float(__ushort_as_bfloat16((unsigned short)(xh8 & 0xFFFF)))
                      + __bfloat162float(__ushort_as_bfloat16((unsigned short)(xl8 & 0xFFFF)));
            float x81 = __bfloat162float(__ushort_as_bfloat16((unsigned short)(xh8 >> 16)))
                      + __bfloat162float(__ushort_as_bfloat16((unsigned short)(xl8 >> 16)));
            float2 o0, o8;
            o0.x = acc[mt][nt][0] + bn0v + x00;
            o0.y = acc[mt][nt][1] + bn1v + x01;
            o8.x = acc[mt][nt][2] + bn0v + x80;
            o8.y = acc[mt][nt][3] + bn1v + x81;
            *reinterpret_cast<float2*>(out + i0) = o0;
            *reinterpret_cast<float2*>(out + i8) = o8;
        }
    }
}

// ---------------- layernorm stats (per batch over T*C) ----------------
__global__ void stats_kernel(const float* __restrict__ src, int which) {
    int b   = blockIdx.x;
    int tid = threadIdx.x;
    const float* base = (which == 0) ? src : g_z;
    const float4* p = reinterpret_cast<const float4*>(base + (size_t)b * TC_);
    float sx = 0.f, sy = 0.f, sz = 0.f, sw = 0.f;
    float qx = 0.f, qy = 0.f, qz = 0.f, qw = 0.f;
    for (int i = tid; i < TC_ / 4; i += 256) {
        float4 v = p[i];
        sx += v.x; sy += v.y; sz += v.z; sw += v.w;
        qx = fmaf(v.x, v.x, qx);
        qy = fmaf(v.y, v.y, qy);
        qz = fmaf(v.z, v.z, qz);
        qw = fmaf(v.w, v.w, qw);
    }
    __shared__ double sh [256];
    __shared__ double sh2[256];
    sh [tid] = (double)sx + (double)sy + (double)sz + (double)sw;
    sh2[tid] = (double)qx + (double)qy + (double)qz + (double)qw;
    __syncthreads();
    for (int off = 128; off > 0; off >>= 1) {
        if (tid < off) { sh[tid] += sh[tid + off]; sh2[tid] += sh2[tid + off]; }
        __syncthreads();
    }
    if (tid == 0) {
        double m   = sh[0]  / (double)TC_;
        double var = sh2[0] / (double)TC_ - m * m;
        g_mu  [which * B_ + b] = (float)m;
        g_rstd[which * B_ + b] = (float)(1.0 / sqrt(var + (double)EPS_));
    }
}

// ---------------- ln1 apply + transpose -> xT hi/lo bf16 [b][c][t] ----------------
__global__ void ln1_transpose(const float* __restrict__ inp,
                              const float* __restrict__ w,
                              const float* __restrict__ bias) {
    __shared__ float tile[32][33];
    int t0 = blockIdx.x * 32, c0 = blockIdx.y * 32, b = blockIdx.z;
    int tid = threadIdx.x;
    float mu = g_mu[b], rs = g_rstd[b];
    const float* src = inp + (size_t)b * TC_;
#pragma unroll
    for (int it = 0; it < 4; ++it) {
        int idx = it * 256 + tid;
        int tr = idx >> 5, tc = idx & 31;
        int gi = (t0 + tr) * C_ + c0 + tc;
        float v = src[gi];
        tile[tr][tc] = fmaf((v - mu) * rs, w[gi], bias[gi]);
    }
    __syncthreads();
    __nv_bfloat16* Xh = g_xTh + (size_t)b * TC_;
    __nv_bfloat16* Xl = g_xTl + (size_t)b * TC_;
#pragma unroll
    for (int it = 0; it < 4; ++it) {
        int idx = it * 256 + tid;
        int cr = idx >> 5, tt = idx & 31;
        float v = tile[tt][cr];
        unsigned short h, l;
        split_bf16(v, h, l);
        size_t o = (size_t)(c0 + cr) * T_ + t0 + tt;
        Xh[o] = __ushort_as_bfloat16(h);
        Xl[o] = __ushort_as_bfloat16(l);
    }
}

// ---------------- ln2 apply: hi/lo bf16 only ----------------
__global__ void apply_ln2(const float* __restrict__ w,
                          const float* __restrict__ bias) {
    int i = blockIdx.x * blockDim.x + threadIdx.x;
    int total = B_ * TC_ / 4;
    if (i >= total) return;
    int b = i / (TC_ / 4);
    int r = i % (TC_ / 4);
    float mu = g_mu[B_ + b];
    float rs = g_rstd[B_ + b];
    float4 v  = reinterpret_cast<const float4*>(g_z)[i];
    float4 wv = reinterpret_cast<const float4*>(w)[r];
    float4 bv = reinterpret_cast<const float4*>(bias)[r];
    v.x = fmaf((v.x - mu) * rs, wv.x, bv.x);
    v.y = fmaf((v.y - mu) * rs, wv.y, bv.y);
    v.z = fmaf((v.z - mu) * rs, wv.z, bv.z);
    v.w = fmaf((v.w - mu) * rs, wv.w, bv.w);
    ushort4 Hh, Ll;
    split_bf16(v.x, Hh.x, Ll.x);
    split_bf16(v.y, Hh.y, Ll.y);
    split_bf16(v.z, Hh.z, Ll.z);
    split_bf16(v.w, Hh.w, Ll.w);
    reinterpret_cast<ushort4*>(g_x2h)[i] = Hh;
    reinterpret_cast<ushort4*>(g_x2l)[i] = Ll;
}

// ---------------- weight hi/lo split kernels ----------------
// IMPORTANT: destinations are referenced INSIDE device code (taking the address
// of a __device__ array in host code passes a bogus host shadow symbol).
__global__ void conv_split_fc1(const float* __restrict__ src) {
    int i = blockIdx.x * blockDim.x + threadIdx.x;
    if (i >= H_ * C_ / 4) return;
    float4 v = reinterpret_cast<const float4*>(src)[i];
    ushort4 Hh, Ll;
    split_bf16(v.x, Hh.x, Ll.x);
    split_bf16(v.y, Hh.y, Ll.y);
    split_bf16(v.z, Hh.z, Ll.z);
    split_bf16(v.w, Hh.w, Ll.w);
    reinterpret_cast<ushort4*>(g_f1h)[i] = Hh;
    reinterpret_cast<ushort4*>(g_f1l)[i] = Ll;
}

__global__ void conv_split_fc2(const float* __restrict__ src) {
    int i = blockIdx.x * blockDim.x + threadIdx.x;
    if (i >= C_ * H_ / 4) return;
    float4 v = reinterpret_cast<const float4*>(src)[i];
    ushort4 Hh, Ll;
    split_bf16(v.x, Hh.x, Ll.x);
    split_bf16(v.y, Hh.y, Ll.y);
    split_bf16(v.z, Hh.z, Ll.z);
    split_bf16(v.w, Hh.w, Ll.w);
    reinterpret_cast<ushort4*>(g_f2h)[i] = Hh;
    reinterpret_cast<ushort4*>(g_f2l)[i] = Ll;
}

__global__ void conv_split_tril(const float* __restrict__ src) {
    int i = blockIdx.x * blockDim.x + threadIdx.x;   // float4 index over T*T
    if (i >= T_ * T_ / 4) return;
    int e0 = i * 4;
    int s = e0 >> 9;          // row
    int t = e0 & 511;         // col of first elem
    float4 v = reinterpret_cast<const float4*>(src)[i];
    if (t + 0 > s) v.x = 0.f;
    if (t + 1 > s) v.y = 0.f;
    if (t + 2 > s) v.z = 0.f;
    if (t + 3 > s) v.w = 0.f;
    ushort4 Hh, Ll;
    split_bf16(v.x, Hh.x, Ll.x);
    split_bf16(v.y, Hh.y, Ll.y);
    split_bf16(v.z, Hh.z, Ll.z);
    split_bf16(v.w, Hh.w, Ll.w);
    reinterpret_cast<ushort4*>(g_wh)[i] = Hh;
    reinterpret_cast<ushort4*>(g_wl)[i] = Ll;
}

// ---------------- launch ----------------
extern "C" void kernel_launch(void* const* d_in, const int* in_sizes, int n_in,
                              void* d_out, int out_size) {
    (void)in_sizes; (void)n_in; (void)out_size;
    const float* inp    = (const float*)d_in[0];
    const float* ln1_w  = (const float*)d_in[1];
    const float* ln1_b  = (const float*)d_in[2];
    const float* ln2_w  = (const float*)d_in[3];
    const float* ln2_b  = (const float*)d_in[4];
    const float* triu_W = (const float*)d_in[5];
    const float* triu_b = (const float*)d_in[6];
    const float* fc1_W  = (const float*)d_in[7];
    const float* fc1_b  = (const float*)d_in[8];
    const float* fc2_W  = (const float*)d_in[9];
    const float* fc2_b  = (const float*)d_in[10];
    float* out = (float*)d_out;

    cudaFuncSetAttribute((const void*)gemm_triu_mma,
                         cudaFuncAttributeMaxDynamicSharedMemorySize, DYN_SMEM);
    cudaFuncSetAttribute((const void*)gemm_fc1_mma,
                         cudaFuncAttributeMaxDynamicSharedMemorySize, DYN_SMEM);
    cudaFuncSetAttribute((const void*)gemm_fc2_mma,
                         cudaFuncAttributeMaxDynamicSharedMemorySize, DYN_SMEM);

    int ew_blocks = (B_ * TC_ / 4 + 255) / 256;

    // weight hi/lo splits (destinations referenced in device code)
    conv_split_tril<<<(T_ * T_ / 4 + 255) / 256, 256>>>(triu_W);
    conv_split_fc1<<<(H_ * C_ / 4 + 255) / 256, 256>>>(fc1_W);
    conv_split_fc2<<<(C_ * H_ / 4 + 255) / 256, 256>>>(fc2_W);

    // 1. ln1 stats + apply+transpose -> xT hi/lo
    stats_kernel<<<B_, 256>>>(inp, 0);
    ln1_transpose<<<dim3(T_ / 32, C_ / 32, B_), 256>>>(inp, ln1_w, ln1_b);

    // 2. TriU causal mix (+bias +residual) -> g_z
    gemm_triu_mma<<<dim3(C_ / 128, T_ / 128, B_), NTHR, DYN_SMEM>>>(triu_b, inp);

    // 3. ln2 stats + apply -> x2 hi/lo
    stats_kernel<<<B_, 256>>>(inp, 1);
    apply_ln2<<<ew_blocks, 256>>>(ln2_w, ln2_b);

    // 4. fc1 + exact GELU -> g_hh/g_hl
    gemm_fc1_mma<<<dim3(H_ / 128, M_ / 128), NTHR, DYN_SMEM>>>(fc1_b);

    // 5. fc2 + bias + residual -> out
    gemm_fc2_mma<<<dim3(C_ / 128, M_ / 128), NTHR, DYN_SMEM>>>(fc2_b, out);
}

// round 9
// speedup vs baseline: 2.2101x; 1.0000x over previous
#include <cuda_runtime.h>
#include <cuda_bf16.h>
#include <math.h>
#include <stdint.h>

// ---------------- problem constants ----------------
#define B_ 128
#define T_ 512
#define C_ 512
#define TC_ (T_ * C_)          // 262144
#define M_ (B_ * T_)           // 65536
#define H_ (2 * C_)            // 1024
#define EPS_ 1e-5f

#define KCE 64                  // k elements per chunk (64 bf16 = 128B row)
#define STG_B 32768             // stage bytes: A tile 16KB + B tile 16KB
#define DYN_SMEM (2 * STG_B)    // 64KB double buffered
#define NTHR 512                // 16 warps

// ---------------- scratch (static device arrays; no allocation) ----------------
__device__ float g_z [(size_t)B_ * TC_];           // triu out + residual (ln2 input)
__device__ __nv_bfloat16 g_x2h[(size_t)B_ * TC_];  // ln2 output hi
__device__ __nv_bfloat16 g_x2l[(size_t)B_ * TC_];  // ln2 output lo
__device__ __nv_bfloat16 g_xTh[(size_t)B_ * TC_];  // ln1 out transposed [b][c][t] hi
__device__ __nv_bfloat16 g_xTl[(size_t)B_ * TC_];  // lo
__device__ __nv_bfloat16 g_hh[(size_t)M_ * H_];    // gelu(fc1) hi
__device__ __nv_bfloat16 g_hl[(size_t)M_ * H_];    // lo
__device__ __nv_bfloat16 g_wh[(size_t)T_ * T_];    // tril(triu_W) hi
__device__ __nv_bfloat16 g_wl[(size_t)T_ * T_];    // lo
__device__ __nv_bfloat16 g_f1h[(size_t)H_ * C_];   // fc1_W hi
__device__ __nv_bfloat16 g_f1l[(size_t)H_ * C_];
__device__ __nv_bfloat16 g_f2h[(size_t)C_ * H_];   // fc2_W hi
__device__ __nv_bfloat16 g_f2l[(size_t)C_ * H_];
__device__ float g_mu  [2 * B_];
__device__ float g_rstd[2 * B_];

// ---------------- small helpers ----------------
__device__ __forceinline__ uint32_t su32(const void* p) {
    uint32_t a;
    asm("{ .reg .u64 t; cvta.to.shared.u64 t, %1; cvt.u32.u64 %0, t; }" : "=r"(a) : "l"(p));
    return a;
}
__device__ __forceinline__ void cp16(uint32_t saddr, const void* g) {
    asm volatile("cp.async.cg.shared.global [%0], [%1], 16;" :: "r"(saddr), "l"(g));
}
__device__ __forceinline__ void cp_commit() {
    asm volatile("cp.async.commit_group;" ::: "memory");
}
__device__ __forceinline__ void cp_wait1() {
    asm volatile("cp.async.wait_group 1;" ::: "memory");
}
__device__ __forceinline__ void cp_wait0() {
    asm volatile("cp.async.wait_group 0;" ::: "memory");
}
__device__ __forceinline__ void ldm_x4(uint32_t& r0, uint32_t& r1, uint32_t& r2, uint32_t& r3,
                                       uint32_t addr) {
    asm volatile("ldmatrix.sync.aligned.m8n8.x4.shared.b16 {%0,%1,%2,%3}, [%4];"
                 : "=r"(r0), "=r"(r1), "=r"(r2), "=r"(r3) : "r"(addr));
}
__device__ __forceinline__ void mma_bf16(float& d0, float& d1, float& d2, float& d3,
                                         uint32_t a0, uint32_t a1, uint32_t a2, uint32_t a3,
                                         uint32_t b0, uint32_t b1) {
    asm volatile(
        "mma.sync.aligned.m16n8k16.row.col.f32.bf16.bf16.f32 "
        "{%0,%1,%2,%3}, {%4,%5,%6,%7}, {%8,%9}, {%0,%1,%2,%3};"
        : "+f"(d0), "+f"(d1), "+f"(d2), "+f"(d3)
        : "r"(a0), "r"(a1), "r"(a2), "r"(a3), "r"(b0), "r"(b1));
}
__device__ __forceinline__ void split_bf16(float v, unsigned short& h, unsigned short& l) {
    __nv_bfloat16 bh = __float2bfloat16(v);
    float fh = __bfloat162float(bh);
    __nv_bfloat16 bl = __float2bfloat16(v - fh);
    h = __bfloat16_as_ushort(bh);
    l = __bfloat16_as_ushort(bl);
}
__device__ __forceinline__ float gelu_exact(float v) {
    return 0.5f * v * (1.0f + erff(v * 0.70710678118654752f));
}

// ---------------- GEMM mainloop pieces ----------------
// smem tile: 128 rows x 128 bytes, swizzled: sw = off ^ ((off>>3)&0x70)
__device__ __forceinline__ void load_chunk(uint32_t sA, uint32_t sB,
                                           const __nv_bfloat16* __restrict__ A, int am0, int lda,
                                           const __nv_bfloat16* __restrict__ Bsrc, int bn0, int ldb,
                                           int k0, int tid) {
#pragma unroll
    for (int it = 0; it < 2; ++it) {
        int idx = it * NTHR + tid;                 // 0..1023
        int r = idx >> 3, g = idx & 7;
        uint32_t off = (r << 7) + (g << 4);
        uint32_t sw = off ^ ((off >> 3) & 0x70);
        cp16(sA + sw, A + (size_t)(am0 + r) * lda + k0 + g * 8);
        cp16(sB + sw, Bsrc + (size_t)(bn0 + r) * ldb + k0 + g * 8);
    }
    cp_commit();
}

// compute one 128x128x64 stage; warp (wm 0..3, wn 0..3) owns 32x32
__device__ __forceinline__ void compute_stage(uint32_t sA, uint32_t sB, int wm, int wn, int lane,
                                              float acc[2][4][4]) {
#pragma unroll
    for (int ks = 0; ks < 4; ++ks) {
        uint32_t a[2][4];
#pragma unroll
        for (int mt = 0; mt < 2; ++mt) {
            int row = wm * 32 + mt * 16 + (lane & 15);
            int col = ks * 32 + ((lane >> 4) << 4);     // bytes
            uint32_t off = (row << 7) + col;
            off ^= (off >> 3) & 0x70;
            ldm_x4(a[mt][0], a[mt][1], a[mt][2], a[mt][3], sA + off);
        }
#pragma unroll
        for (int nt = 0; nt < 2; ++nt) {
            int row = wn * 32 + nt * 16 + ((lane >> 4) << 3) + (lane & 7);
            int col = ks * 32 + (((lane >> 3) & 1) << 4);  // bytes
            uint32_t off = (row << 7) + col;
            off ^= (off >> 3) & 0x70;
            uint32_t b0, b1, b2, b3;
            ldm_x4(b0, b1, b2, b3, sB + off);
#pragma unroll
            for (int mt = 0; mt < 2; ++mt) {
                mma_bf16(acc[mt][2 * nt + 0][0], acc[mt][2 * nt + 0][1],
                         acc[mt][2 * nt + 0][2], acc[mt][2 * nt + 0][3],
                         a[mt][0], a[mt][1], a[mt][2], a[mt][3], b0, b1);
                mma_bf16(acc[mt][2 * nt + 1][0], acc[mt][2 * nt + 1][1],
                         acc[mt][2 * nt + 1][2], acc[mt][2 * nt + 1][3],
                         a[mt][0], a[mt][1], a[mt][2], a[mt][3], b2, b3);
            }
        }
    }
}

// 3-pass hi/lo K-extended mainloop: p0=Ah*Bh, p1=Al*Bh, p2=Ah*Bl
#define GEMM_MAINLOOP(AH, AL, BH, BL, AM0, LDA, BN0, LDB, NK)                              \
    int nk = (NK);                                                                          \
    int ntot = 3 * nk;                                                                      \
    float acc[2][4][4];                                                                     \
    _Pragma("unroll") for (int i_ = 0; i_ < 2; ++i_)                                        \
    _Pragma("unroll") for (int j_ = 0; j_ < 4; ++j_)                                        \
    _Pragma("unroll") for (int e_ = 0; e_ < 4; ++e_) acc[i_][j_][e_] = 0.f;                 \
    load_chunk(sbase, sbase + 16384, (AH), (AM0), (LDA), (BH), (BN0), (LDB), 0, tid);       \
    for (int q = 0; q < ntot; ++q) {                                                        \
        if (q + 1 < ntot) {                                                                 \
            int qn = q + 1;                                                                 \
            int p_ = qn / nk;                                                               \
            int k0_ = (qn - p_ * nk) * KCE;                                                 \
            const __nv_bfloat16* As_ = (p_ == 1) ? (AL) : (AH);                             \
            const __nv_bfloat16* Bs_ = (p_ == 2) ? (BL) : (BH);                             \
            uint32_t sb = sbase + (qn & 1) * STG_B;                                         \
            load_chunk(sb, sb + 16384, As_, (AM0), (LDA), Bs_, (BN0), (LDB), k0_, tid);     \
            cp_wait1();                                                                     \
        } else {                                                                            \
            cp_wait0();                                                                     \
        }                                                                                   \
        __syncthreads();                                                                    \
        uint32_t sc = sbase + (q & 1) * STG_B;                                              \
        compute_stage(sc, sc + 16384, wm, wn, lane, acc);                                   \
        __syncthreads();                                                                    \
    }

// ---------------- TriU GEMM: g_z[b,s,c] = sum_{t<=s} W[s,t]*x[b,t,c] + tb[s] + inp[b,s,c]
__global__ void __launch_bounds__(NTHR, 1)
gemm_triu_mma(const float* __restrict__ tb, const float* __restrict__ inp) {
    extern __shared__ __align__(128) char dyn[];
    uint32_t sbase = su32(dyn);
    int tid = threadIdx.x, lane = tid & 31, w = tid >> 5, wm = w & 3, wn = w >> 2;
    int bx = blockIdx.x, by = blockIdx.y, bz = blockIdx.z;
    int m0 = by * 128, n0 = bx * 128;
    const __nv_bfloat16* Bh = g_xTh + (size_t)bz * TC_;
    const __nv_bfloat16* Bl = g_xTl + (size_t)bz * TC_;

    GEMM_MAINLOOP(g_wh, g_wl, Bh, Bl, m0, T_, n0, T_, 2 * (by + 1))

    float* Z = g_z + (size_t)bz * TC_;
    const float* I = inp + (size_t)bz * TC_;
#pragma unroll
    for (int mt = 0; mt < 2; ++mt) {
        int m = m0 + wm * 32 + mt * 16 + (lane >> 2);
        float tbm = tb[m], tbm8 = tb[m + 8];
#pragma unroll
        for (int nt = 0; nt < 4; ++nt) {
            int n = n0 + wn * 32 + nt * 8 + 2 * (lane & 3);
            size_t i0 = (size_t)m * C_ + n;
            size_t i8 = (size_t)(m + 8) * C_ + n;
            float2 r0 = *reinterpret_cast<const float2*>(I + i0);
            float2 r8 = *reinterpret_cast<const float2*>(I + i8);
            float2 o0, o8;
            o0.x = acc[mt][nt][0] + tbm + r0.x;
            o0.y = acc[mt][nt][1] + tbm + r0.y;
            o8.x = acc[mt][nt][2] + tbm8 + r8.x;
            o8.y = acc[mt][nt][3] + tbm8 + r8.y;
            *reinterpret_cast<float2*>(Z + i0) = o0;
            *reinterpret_cast<float2*>(Z + i8) = o8;
        }
    }
}

// ---------------- fc1 GEMM: h = gelu(x2 @ fc1_W^T + b1) -> hi/lo bf16
__global__ void __launch_bounds__(NTHR, 1)
gemm_fc1_mma(const float* __restrict__ b1) {
    extern __shared__ __align__(128) char dyn[];
    uint32_t sbase = su32(dyn);
    int tid = threadIdx.x, lane = tid & 31, w = tid >> 5, wm = w & 3, wn = w >> 2;
    int bx = blockIdx.x, by = blockIdx.y;
    int m0 = by * 128, n0 = bx * 128;

    GEMM_MAINLOOP(g_x2h, g_x2l, g_f1h, g_f1l, m0, C_, n0, C_, C_ / KCE)

#pragma unroll
    for (int mt = 0; mt < 2; ++mt) {
        int m = m0 + wm * 32 + mt * 16 + (lane >> 2);
#pragma unroll
        for (int nt = 0; nt < 4; ++nt) {
            int n = n0 + wn * 32 + nt * 8 + 2 * (lane & 3);
            float bn0v = b1[n], bn1v = b1[n + 1];
            float v0 = gelu_exact(acc[mt][nt][0] + bn0v);
            float v1 = gelu_exact(acc[mt][nt][1] + bn1v);
            float v2 = gelu_exact(acc[mt][nt][2] + bn0v);
            float v3 = gelu_exact(acc[mt][nt][3] + bn1v);
            unsigned short h0, l0, h1, l1, h2, l2, h3, l3;
            split_bf16(v0, h0, l0);
            split_bf16(v1, h1, l1);
            split_bf16(v2, h2, l2);
            split_bf16(v3, h3, l3);
            size_t i0 = (size_t)m * H_ + n;
            size_t i8 = (size_t)(m + 8) * H_ + n;
            *reinterpret_cast<uint32_t*>(g_hh + i0) = (uint32_t)h0 | ((uint32_t)h1 << 16);
            *reinterpret_cast<uint32_t*>(g_hl + i0) = (uint32_t)l0 | ((uint32_t)l1 << 16);
            *reinterpret_cast<uint32_t*>(g_hh + i8) = (uint32_t)h2 | ((uint32_t)h3 << 16);
            *reinterpret_cast<uint32_t*>(g_hl + i8) = (uint32_t)l2 | ((uint32_t)l3 << 16);
        }
    }
}

// ---------------- fc2 GEMM: out = h @ fc2_W^T + b2 + x2 (residual from hi+lo)
__global__ void __launch_bounds__(NTHR, 1)
gemm_fc2_mma(const float* __restrict__ b2, float* __restrict__ out) {
    extern __shared__ __align__(128) char dyn[];
    uint32_t sbase = su32(dyn);
    int tid = threadIdx.x, lane = tid & 31, w = tid >> 5, wm = w & 3, wn = w >> 2;
    int bx = blockIdx.x, by = blockIdx.y;
    int m0 = by * 128, n0 = bx * 128;

    GEMM_MAINLOOP(g_hh, g_hl, g_f2h, g_f2l, m0, H_, n0, H_, H_ / KCE)

#pragma unroll
    for (int mt = 0; mt < 2; ++mt) {
        int m = m0 + wm * 32 + mt * 16 + (lane >> 2);
#pragma unroll
        for (int nt = 0; nt < 4; ++nt) {
            int n = n0 + wn * 32 + nt * 8 + 2 * (lane & 3);
            float bn0v = b2[n], bn1v = b2[n + 1];
            size_t i0 = (size_t)m * C_ + n;
            size_t i8 = (size_t)(m + 8) * C_ + n;
            uint32_t xh0 = *reinterpret_cast<const uint32_t*>(g_x2h + i0);
            uint32_t xl0 = *reinterpret_cast<const uint32_t*>(g_x2l + i0);
            uint32_t xh8 = *reinterpret_cast<const uint32_t*>(g_x2h + i8);
            uint32_t xl8 = *reinterpret_cast<const uint32_t*>(g_x2l + i8);
            float x00 = __bfloat162float(__ushort_as_bfloat16((unsigned short)(xh0 & 0xFFFF)))
                      + __bfloat162float(__ushort_as_bfloat16((unsigned short)(xl0 & 0xFFFF)));
            float x01 = __bfloat162float(__ushort_as_bfloat16((unsigned short)(xh0 >> 16)))
                      + __bfloat162float(__ushort_as_bfloat16((unsigned short)(xl0 >> 16)));
            float x80 = __bfloat162float(__ushort_as_bfloat16((unsigned short)(xh8 & 0xFFFF)))
                      + __bfloat162float(__ushort_as_bfloat16((unsigned short)(xl8 & 0xFFFF)));
            float x81 = __bfloat162float(__ushort_as_bfloat16((unsigned short)(xh8 >> 16)))
                      + __bfloat162float(__ushort_as_bfloat16((unsigned short)(xl8 >> 16)));
            float2 o0, o8;
            o0.x = acc[mt][nt][0] + bn0v + x00;
            o0.y = acc[mt][nt][1] + bn1v + x01;
            o8.x = acc[mt][nt][2] + bn0v + x80;
            o8.y = acc[mt][nt][3] + bn1v + x81;
            *reinterpret_cast<float2*>(out + i0) = o0;
            *reinterpret_cast<float2*>(out + i8) = o8;
        }
    }
}

// ---------------- layernorm stats (per batch over T*C) ----------------
__global__ void stats_kernel(const float* __restrict__ src, int which) {
    int b   = blockIdx.x;
    int tid = threadIdx.x;
    const float* base = (which == 0) ? src : g_z;
    const float4* p = reinterpret_cast<const float4*>(base + (size_t)b * TC_);
    float sx = 0.f, sy = 0.f, sz = 0.f, sw = 0.f;
    float qx = 0.f, qy = 0.f, qz = 0.f, qw = 0.f;
    for (int i = tid; i < TC_ / 4; i += 256) {
        float4 v = p[i];
        sx += v.x; sy += v.y; sz += v.z; sw += v.w;
        qx = fmaf(v.x, v.x, qx);
        qy = fmaf(v.y, v.y, qy);
        qz = fmaf(v.z, v.z, qz);
        qw = fmaf(v.w, v.w, qw);
    }
    __shared__ double sh [256];
    __shared__ double sh2[256];
    sh [tid] = (double)sx + (double)sy + (double)sz + (double)sw;
    sh2[tid] = (double)qx + (double)qy + (double)qz + (double)qw;
    __syncthreads();
    for (int off = 128; off > 0; off >>= 1) {
        if (tid < off) { sh[tid] += sh[tid + off]; sh2[tid] += sh2[tid + off]; }
        __syncthreads();
    }
    if (tid == 0) {
        double m   = sh[0]  / (double)TC_;
        double var = sh2[0] / (double)TC_ - m * m;
        g_mu  [which * B_ + b] = (float)m;
        g_rstd[which * B_ + b] = (float)(1.0 / sqrt(var + (double)EPS_));
    }
}

// ---------------- ln1 apply + transpose -> xT hi/lo bf16 [b][c][t] ----------------
__global__ void ln1_transpose(const float* __restrict__ inp,
                              const float* __restrict__ w,
                              const float* __restrict__ bias) {
    __shared__ float tile[32][33];
    int t0 = blockIdx.x * 32, c0 = blockIdx.y * 32, b = blockIdx.z;
    int tid = threadIdx.x;
    float mu = g_mu[b], rs = g_rstd[b];
    const float* src = inp + (size_t)b * TC_;
#pragma unroll
    for (int it = 0; it < 4; ++it) {
        int idx = it * 256 + tid;
        int tr = idx >> 5, tc = idx & 31;
        int gi = (t0 + tr) * C_ + c0 + tc;
        float v = src[gi];
        tile[tr][tc] = fmaf((v - mu) * rs, w[gi], bias[gi]);
    }
    __syncthreads();
    __nv_bfloat16* Xh = g_xTh + (size_t)b * TC_;
    __nv_bfloat16* Xl = g_xTl + (size_t)b * TC_;
#pragma unroll
    for (int it = 0; it < 4; ++it) {
        int idx = it * 256 + tid;
        int cr = idx >> 5, tt = idx & 31;
        float v = tile[tt][cr];
        unsigned short h, l;
        split_bf16(v, h, l);
        size_t o = (size_t)(c0 + cr) * T_ + t0 + tt;
        Xh[o] = __ushort_as_bfloat16(h);
        Xl[o] = __ushort_as_bfloat16(l);
    }
}

// ---------------- ln2 apply: hi/lo bf16 only ----------------
__global__ void apply_ln2(const float* __restrict__ w,
                          const float* __restrict__ bias) {
    int i = blockIdx.x * blockDim.x + threadIdx.x;
    int total = B_ * TC_ / 4;
    if (i >= total) return;
    int b = i / (TC_ / 4);
    int r = i % (TC_ / 4);
    float mu = g_mu[B_ + b];
    float rs = g_rstd[B_ + b];
    float4 v  = reinterpret_cast<const float4*>(g_z)[i];
    float4 wv = reinterpret_cast<const float4*>(w)[r];
    float4 bv = reinterpret_cast<const float4*>(bias)[r];
    v.x = fmaf((v.x - mu) * rs, wv.x, bv.x);
    v.y = fmaf((v.y - mu) * rs, wv.y, bv.y);
    v.z = fmaf((v.z - mu) * rs, wv.z, bv.z);
    v.w = fmaf((v.w - mu) * rs, wv.w, bv.w);
    ushort4 Hh, Ll;
    split_bf16(v.x, Hh.x, Ll.x);
    split_bf16(v.y, Hh.y, Ll.y);
    split_bf16(v.z, Hh.z, Ll.z);
    split_bf16(v.w, Hh.w, Ll.w);
    reinterpret_cast<ushort4*>(g_x2h)[i] = Hh;
    reinterpret_cast<ushort4*>(g_x2l)[i] = Ll;
}

// ---------------- weight hi/lo split kernels ----------------
// IMPORTANT: destinations are referenced INSIDE device code (taking the address
// of a __device__ array in host code passes a bogus host shadow symbol).
__global__ void conv_split_fc1(const float* __restrict__ src) {
    int i = blockIdx.x * blockDim.x + threadIdx.x;
    if (i >= H_ * C_ / 4) return;
    float4 v = reinterpret_cast<const float4*>(src)[i];
    ushort4 Hh, Ll;
    split_bf16(v.x, Hh.x, Ll.x);
    split_bf16(v.y, Hh.y, Ll.y);
    split_bf16(v.z, Hh.z, Ll.z);
    split_bf16(v.w, Hh.w, Ll.w);
    reinterpret_cast<ushort4*>(g_f1h)[i] = Hh;
    reinterpret_cast<ushort4*>(g_f1l)[i] = Ll;
}

__global__ void conv_split_fc2(const float* __restrict__ src) {
    int i = blockIdx.x * blockDim.x + threadIdx.x;
    if (i >= C_ * H_ / 4) return;
    float4 v = reinterpret_cast<const float4*>(src)[i];
    ushort4 Hh, Ll;
    split_bf16(v.x, Hh.x, Ll.x);
    split_bf16(v.y, Hh.y, Ll.y);
    split_bf16(v.z, Hh.z, Ll.z);
    split_bf16(v.w, Hh.w, Ll.w);
    reinterpret_cast<ushort4*>(g_f2h)[i] = Hh;
    reinterpret_cast<ushort4*>(g_f2l)[i] = Ll;
}

__global__ void conv_split_tril(const float* __restrict__ src) {
    int i = blockIdx.x * blockDim.x + threadIdx.x;   // float4 index over T*T
    if (i >= T_ * T_ / 4) return;
    int e0 = i * 4;
    int s = e0 >> 9;          // row
    int t = e0 & 511;         // col of first elem
    float4 v = reinterpret_cast<const float4*>(src)[i];
    if (t + 0 > s) v.x = 0.f;
    if (t + 1 > s) v.y = 0.f;
    if (t + 2 > s) v.z = 0.f;
    if (t + 3 > s) v.w = 0.f;
    ushort4 Hh, Ll;
    split_bf16(v.x, Hh.x, Ll.x);
    split_bf16(v.y, Hh.y, Ll.y);
    split_bf16(v.z, Hh.z, Ll.z);
    split_bf16(v.w, Hh.w, Ll.w);
    reinterpret_cast<ushort4*>(g_wh)[i] = Hh;
    reinterpret_cast<ushort4*>(g_wl)[i] = Ll;
}

// ---------------- launch ----------------
extern "C" void kernel_launch(void* const* d_in, const int* in_sizes, int n_in,
                              void* d_out, int out_size) {
    (void)in_sizes; (void)n_in; (void)out_size;
    const float* inp    = (const float*)d_in[0];
    const float* ln1_w  = (const float*)d_in[1];
    const float* ln1_b  = (const float*)d_in[2];
    const float* ln2_w  = (const float*)d_in[3];
    const float* ln2_b  = (const float*)d_in[4];
    const float* triu_W = (const float*)d_in[5];
    const float* triu_b = (const float*)d_in[6];
    const float* fc1_W  = (const float*)d_in[7];
    const float* fc1_b  = (const float*)d_in[8];
    const float* fc2_W  = (const float*)d_in[9];
    const float* fc2_b  = (const float*)d_in[10];
    float* out = (float*)d_out;

    cudaFuncSetAttribute((const void*)gemm_triu_mma,
                         cudaFuncAttributeMaxDynamicSharedMemorySize, DYN_SMEM);
    cudaFuncSetAttribute((const void*)gemm_fc1_mma,
                         cudaFuncAttributeMaxDynamicSharedMemorySize, DYN_SMEM);
    cudaFuncSetAttribute((const void*)gemm_fc2_mma,
                         cudaFuncAttributeMaxDynamicSharedMemorySize, DYN_SMEM);

    int ew_blocks = (B_ * TC_ / 4 + 255) / 256;

    // weight hi/lo splits (destinations referenced in device code)
    conv_split_tril<<<(T_ * T_ / 4 + 255) / 256, 256>>>(triu_W);
    conv_split_fc1<<<(H_ * C_ / 4 + 255) / 256, 256>>>(fc1_W);
    conv_split_fc2<<<(C_ * H_ / 4 + 255) / 256, 256>>>(fc2_W);

    // 1. ln1 stats + apply+transpose -> xT hi/lo
    stats_kernel<<<B_, 256>>>(inp, 0);
    ln1_transpose<<<dim3(T_ / 32, C_ / 32, B_), 256>>>(inp, ln1_w, ln1_b);

    // 2. TriU causal mix (+bias +residual) -> g_z
    gemm_triu_mma<<<dim3(C_ / 128, T_ / 128, B_), NTHR, DYN_SMEM>>>(triu_b, inp);

    // 3. ln2 stats + apply -> x2 hi/lo
    stats_kernel<<<B_, 256>>>(inp, 1);
    apply_ln2<<<ew_blocks, 256>>>(ln2_w, ln2_b);

    // 4. fc1 + exact GELU -> g_hh/g_hl
    gemm_fc1_mma<<<dim3(H_ / 128, M_ / 128), NTHR, DYN_SMEM>>>(fc1_b);

    // 5. fc2 + bias + residual -> out
    gemm_fc2_mma<<<dim3(C_ / 128, M_ / 128), NTHR, DYN_SMEM>>>(fc2_b, out);
}